// round 14
// baseline (speedup 1.0000x reference)
#include <cuda_runtime.h>
#include <cuda_fp16.h>
#include <cstdint>

#define BATCH 8
#define SEQ   2048
#define DIMM  512
#define HEADS 8
#define DH    64
#define INNER 512
#define QKVC  1536
#define FULLM 0xffffffffu

// Scratch (fp16, static device globals — allocation-free)
__device__ __half g_xh[(size_t)BATCH * SEQ * DIMM];
__device__ __half g_wqkvh[(size_t)DIMM * QKVC];
__device__ __half g_wouth[(size_t)INNER * DIMM];
__device__ __half g_qkv[(size_t)BATCH * SEQ * QKVC];    // [b,n,3*inner]
__device__ __half g_att[(size_t)BATCH * SEQ * INNER];   // [b,n,h*64+d]

// ---------------------------------------------------------------------------
__device__ __forceinline__ uint32_t smem_u32(const void* p) {
    uint32_t a;
    asm("{ .reg .u64 t; cvta.to.shared.u64 t, %1; cvt.u32.u64 %0, t; }"
        : "=r"(a) : "l"(p));
    return a;
}
__device__ __forceinline__ void cp16(uint32_t s, const void* g) {
    asm volatile("cp.async.cg.shared.global [%0], [%1], 16;"
                 :: "r"(s), "l"(g) : "memory");
}
__device__ __forceinline__ void cp_commit() {
    asm volatile("cp.async.commit_group;" ::: "memory");
}
template<int N> __device__ __forceinline__ void cp_wait() {
    asm volatile("cp.async.wait_group %0;" :: "n"(N) : "memory");
}
__device__ __forceinline__ void ldsm_x4(uint32_t addr, uint32_t* r) {
    asm volatile("ldmatrix.sync.aligned.m8n8.x4.shared.b16 {%0,%1,%2,%3}, [%4];"
                 : "=r"(r[0]), "=r"(r[1]), "=r"(r[2]), "=r"(r[3]) : "r"(addr));
}
__device__ __forceinline__ void ldsm_x4t(uint32_t addr, uint32_t* r) {
    asm volatile("ldmatrix.sync.aligned.m8n8.x4.trans.shared.b16 {%0,%1,%2,%3}, [%4];"
                 : "=r"(r[0]), "=r"(r[1]), "=r"(r[2]), "=r"(r[3]) : "r"(addr));
}
__device__ __forceinline__ void ldsm_x2t(uint32_t addr, uint32_t* r) {
    asm volatile("ldmatrix.sync.aligned.m8n8.x2.trans.shared.b16 {%0,%1}, [%2];"
                 : "=r"(r[0]), "=r"(r[1]) : "r"(addr));
}
__device__ __forceinline__ void mma16(float* d, const uint32_t* a,
                                      uint32_t b0, uint32_t b1) {
    asm volatile(
        "mma.sync.aligned.m16n8k16.row.col.f32.f16.f16.f32 "
        "{%0,%1,%2,%3}, {%4,%5,%6,%7}, {%8,%9}, {%0,%1,%2,%3};"
        : "+f"(d[0]), "+f"(d[1]), "+f"(d[2]), "+f"(d[3])
        : "r"(a[0]), "r"(a[1]), "r"(a[2]), "r"(a[3]), "r"(b0), "r"(b1));
}
__device__ __forceinline__ uint32_t packh2(float x, float y) {
    const __half2 h = __floats2half2_rn(x, y);
    return *(const uint32_t*)&h;
}
__device__ __forceinline__ float ex2(float x) {
    float r;
    asm("ex2.approx.f32 %0, %1;" : "=f"(r) : "f"(x));
    return r;
}

// ---------------------------------------------------------------------------
// Merged fp32 -> fp16 convert over three segments (sizes in float4 chunks).
// ---------------------------------------------------------------------------
__global__ __launch_bounds__(256) void f2h3(
    const float* __restrict__ s0, __half* __restrict__ d0, int n0,
    const float* __restrict__ s1, __half* __restrict__ d1, int n1,
    const float* __restrict__ s2, __half* __restrict__ d2)
{
    int blk = blockIdx.x;
    const float* src;
    __half* dst;
    if (blk < n0)            { src = s0; dst = d0; }
    else if (blk < n0 + n1)  { src = s1; dst = d1; blk -= n0; }
    else                     { src = s2; dst = d2; blk -= n0 + n1; }
    const int i = (blk * 256 + threadIdx.x) * 4;
    const float4 v = *(const float4*)(src + i);
    uint2 h;
    h.x = packh2(v.x, v.y);
    h.y = packh2(v.z, v.w);
    *(uint2*)(dst + i) = h;
}

// ---------------------------------------------------------------------------
// fp16 GEMM, occupancy-optimized: block 128x64, warp tile 32x32, BK=32,
// 3-stage cp.async with STRICT one-commit-per-iteration cadence (dummy
// commit on tail iterations -> wait<1> always guards the consumed stage).
// __launch_bounds__(256,3) -> 3 CTAs/SM, 24 warps/SM.
// ---------------------------------------------------------------------------
template<bool C_HALF, bool BIAS>
__global__ __launch_bounds__(256, 3) void gemm_h(
    const __half* __restrict__ A, const __half* __restrict__ Bg,
    const float* __restrict__ bias, void* __restrict__ Cv,
    int M, int N, int K)
{
    extern __shared__ __half smg[];
    constexpr uint32_t ASZ = 128 * 40 * 2;     // A: [128][32] pitch 40 halves
    constexpr uint32_t BSZ = 32 * 72 * 2;      // B: [32][64]  pitch 72 halves
    constexpr uint32_t SSZ = ASZ + BSZ;        // 14848 B per stage
    const uint32_t smb = smem_u32(smg);

    const int tid = threadIdx.x;
    const int wid = tid >> 5, lane = tid & 31;
    const int g = lane >> 2, t = lane & 3;
    const int wm = wid & 3, wn = wid >> 2;     // 4(M) x 2(N)
    const int row0 = blockIdx.y * 128;
    const int col0 = blockIdx.x * 64;

    float acc[2][4][4];
#pragma unroll
    for (int mt = 0; mt < 2; mt++)
#pragma unroll
        for (int nt = 0; nt < 4; nt++)
#pragma unroll
            for (int i = 0; i < 4; i++) acc[mt][nt][i] = 0.f;

    auto load_tile = [&](int kb, int st) {
        const uint32_t ab = smb + st * SSZ;
        const uint32_t bb = ab + ASZ;
#pragma unroll
        for (int it = 0; it < 2; it++) {          // A: 512 16B-chunks
            const int idx = tid + 256 * it;
            const int r = idx >> 2, c = (idx & 3) << 3;
            cp16(ab + (r * 40 + c) * 2, A + (size_t)(row0 + r) * K + kb + c);
        }
        {                                         // B: 256 16B-chunks
            const int r = tid >> 3, c = (tid & 7) << 3;
            cp16(bb + (r * 72 + c) * 2, Bg + (size_t)(kb + r) * N + col0 + c);
        }
        cp_commit();
    };

    const int nch = K >> 5;
    load_tile(0, 0);
    load_tile(32, 1);

    int st = 0;
    for (int ch = 0; ch < nch; ch++) {
        cp_wait<1>();
        __syncthreads();
        if (ch + 2 < nch) {
            int ns = st + 2; if (ns >= 3) ns -= 3;
            load_tile((ch + 2) << 5, ns);
        } else {
            cp_commit();   // keep commit cadence: wait<1> stays exact at tail
        }

        const uint32_t asb = smb + st * SSZ;
        const uint32_t bsb = asb + ASZ;
#pragma unroll
        for (int kk = 0; kk < 32; kk += 16) {
            uint32_t a[2][4];
#pragma unroll
            for (int mt = 0; mt < 2; mt++) {
                const int r = wm * 32 + mt * 16 + (lane & 15);
                ldsm_x4(asb + (r * 40 + kk + ((lane >> 4) & 1) * 8) * 2, a[mt]);
            }
#pragma unroll
            for (int bp = 0; bp < 2; bp++) {
                uint32_t b[4];
                const int kr = kk + (lane & 7) + (lane & 8);
                const int nc = wn * 32 + bp * 16 + ((lane >> 4) & 1) * 8;
                ldsm_x4t(bsb + (kr * 72 + nc) * 2, b);
                mma16(acc[0][2 * bp],     a[0], b[0], b[1]);
                mma16(acc[0][2 * bp + 1], a[0], b[2], b[3]);
                mma16(acc[1][2 * bp],     a[1], b[0], b[1]);
                mma16(acc[1][2 * bp + 1], a[1], b[2], b[3]);
            }
        }
        if (++st == 3) st = 0;
    }

#pragma unroll
    for (int mt = 0; mt < 2; mt++) {
        const int r_lo = row0 + wm * 32 + mt * 16 + g;
#pragma unroll
        for (int nt = 0; nt < 4; nt++) {
            const int c = col0 + wn * 32 + nt * 8 + 2 * t;
            if (C_HALF) {
                __half* C = (__half*)Cv;
                *(uint32_t*)(C + (size_t)r_lo * N + c) =
                    packh2(acc[mt][nt][0], acc[mt][nt][1]);
                *(uint32_t*)(C + (size_t)(r_lo + 8) * N + c) =
                    packh2(acc[mt][nt][2], acc[mt][nt][3]);
            } else {
                float* C = (float*)Cv;
                float2 lo = make_float2(acc[mt][nt][0], acc[mt][nt][1]);
                float2 hi = make_float2(acc[mt][nt][2], acc[mt][nt][3]);
                if (BIAS) {
                    lo.x += bias[c]; lo.y += bias[c + 1];
                    hi.x += bias[c]; hi.y += bias[c + 1];
                }
                *(float2*)(C + (size_t)r_lo * N + c) = lo;
                *(float2*)(C + (size_t)(r_lo + 8) * N + c) = hi;
            }
        }
    }
}

// ---------------------------------------------------------------------------
// Fused flash attention: 3-stage cp.async K/V pipeline with strict commit
// cadence (dummy commit at tail), scale*log2e folded into Q, fp32 ex2
// (no max), row sums via ones-column MMA, diag-mask path only on the
// 2 tiles containing the diagonal. Block = (b,h,128 rows), 8 warps.
// ---------------------------------------------------------------------------
__global__ __launch_bounds__(256, 2) void attn_kernel(
    const __half* __restrict__ qkv, const float* __restrict__ lsp,
    __half* __restrict__ att)
{
    extern __shared__ __half sm[];
    constexpr uint32_t QSZ = 128 * 72 * 2;     // 18432 B
    constexpr uint32_t KSZ = 64 * 72 * 2;      // 9216 B per K or V tile
    const uint32_t smb = smem_u32(sm);

    const int i0 = blockIdx.x * 128;
    const int h = blockIdx.y;
    const int b = blockIdx.z;
    const int tid = threadIdx.x;
    const int wid = tid >> 5, lane = tid & 31;
    const int g = lane >> 2, t = lane & 3;

    const __half* qbase = qkv + ((size_t)b * SEQ) * QKVC + h * DH;
    const __half* kbase = qbase + INNER;
    const __half* vbase = qbase + 2 * INNER;
    const float c2 = __expf(lsp[0]) * 1.4426950408889634f;
    const __half2 c2h = __float2half2_rn(c2);

    auto load_kv = [&](int j0, int st) {
        const uint32_t kb = smb + QSZ + st * 2 * KSZ;
#pragma unroll
        for (int it = 0; it < 2; it++) {
            const int idx = tid + 256 * it;
            const int j = idx >> 3, c = (idx & 7) << 3;
            cp16(kb + (j * 72 + c) * 2, kbase + (size_t)(j0 + j) * QKVC + c);
            cp16(kb + KSZ + (j * 72 + c) * 2, vbase + (size_t)(j0 + j) * QKVC + c);
        }
        cp_commit();
    };

    load_kv(0, 0);
    load_kv(64, 1);

    // ---- Ones pad columns (V cols 64..71) for all 3 stages (cp.async never
    //      touches cols >= 64, so no overlap with in-flight loads) ----
    if (tid < 192) {
        const int strow = tid / 64, row = tid & 63;
        const uint32_t voff = QSZ + strow * 2 * KSZ + KSZ;
        const __half2 one2 = __floats2half2_rn(1.f, 1.f);
        uint2 ones;
        ones.x = *(const uint32_t*)&one2;
        ones.y = ones.x;
        *(uint2*)((char*)sm + voff + (row * 72 + 64) * 2) = ones;
        *(uint2*)((char*)sm + voff + (row * 72 + 68) * 2) = ones;
    }

    // ---- Stage Q tile, folding c2 into the fp16 values ----
#pragma unroll
    for (int it = 0; it < 4; it++) {
        const int idx = tid + 256 * it;
        const int r = idx >> 3, c8 = (idx & 7) << 3;
        uint4 v = *(const uint4*)(qbase + (size_t)(i0 + r) * QKVC + c8);
        __half2* hv = (__half2*)&v;
        hv[0] = __hmul2(hv[0], c2h);
        hv[1] = __hmul2(hv[1], c2h);
        hv[2] = __hmul2(hv[2], c2h);
        hv[3] = __hmul2(hv[3], c2h);
        *(uint4*)(sm + r * 72 + c8) = v;
    }
    __syncthreads();

    uint32_t qf[4][4];
#pragma unroll
    for (int kq = 0; kq < 4; kq++) {
        const int r = wid * 16 + (lane & 15);
        ldsm_x4(smb + (r * 72 + kq * 16 + ((lane >> 4) & 1) * 8) * 2, qf[kq]);
    }

    float o[8][4], osum[4];
#pragma unroll
    for (int nt = 0; nt < 8; nt++)
#pragma unroll
        for (int i = 0; i < 4; i++) o[nt][i] = 0.f;
#pragma unroll
    for (int i = 0; i < 4; i++) osum[i] = 0.f;

    const int i_lo = i0 + wid * 16 + g;
    const int i_hi = i_lo + 8;

    int st = 0;
    for (int j0 = 0; j0 < SEQ; j0 += 64) {
        cp_wait<1>();
        __syncthreads();
        if (j0 + 128 < SEQ) {
            int ns = st + 2; if (ns >= 3) ns -= 3;
            load_kv(j0 + 128, ns);
        } else {
            cp_commit();   // keep commit cadence: wait<1> stays exact at tail
        }

        const uint32_t ksb = smb + QSZ + st * 2 * KSZ;
        const uint32_t vsb = ksb + KSZ;

        // ---- S = (Q*c2) K^T ----
        float s[8][4];
#pragma unroll
        for (int nt = 0; nt < 8; nt++)
#pragma unroll
            for (int i = 0; i < 4; i++) s[nt][i] = 0.f;
#pragma unroll
        for (int kq = 0; kq < 4; kq++) {
#pragma unroll
            for (int bp = 0; bp < 4; bp++) {
                uint32_t kb4[4];
                const int jr = bp * 16 + ((lane >> 4) & 1) * 8 + (lane & 7);
                const int kc = kq * 16 + (lane & 8);
                ldsm_x4(ksb + (jr * 72 + kc) * 2, kb4);
                mma16(s[2 * bp],     qf[kq], kb4[0], kb4[1]);
                mma16(s[2 * bp + 1], qf[kq], kb4[2], kb4[3]);
            }
        }

        // ---- p = exp2(s); diag -> 0 only on the 2 tiles containing it ----
        if (j0 == i0 || j0 == i0 + 64) {
#pragma unroll
            for (int nt = 0; nt < 8; nt++) {
                const int jc = j0 + nt * 8 + 2 * t;
                s[nt][0] = ex2((i_lo == jc)     ? -1e4f : s[nt][0]);
                s[nt][1] = ex2((i_lo == jc + 1) ? -1e4f : s[nt][1]);
                s[nt][2] = ex2((i_hi == jc)     ? -1e4f : s[nt][2]);
                s[nt][3] = ex2((i_hi == jc + 1) ? -1e4f : s[nt][3]);
            }
        } else {
#pragma unroll
            for (int nt = 0; nt < 8; nt++) {
                s[nt][0] = ex2(s[nt][0]);
                s[nt][1] = ex2(s[nt][1]);
                s[nt][2] = ex2(s[nt][2]);
                s[nt][3] = ex2(s[nt][3]);
            }
        }

        // ---- O += P V; row sums via ones-column mma ----
#pragma unroll
        for (int q = 0; q < 4; q++) {
            uint32_t a[4];
            a[0] = packh2(s[2 * q][0],     s[2 * q][1]);
            a[1] = packh2(s[2 * q][2],     s[2 * q][3]);
            a[2] = packh2(s[2 * q + 1][0], s[2 * q + 1][1]);
            a[3] = packh2(s[2 * q + 1][2], s[2 * q + 1][3]);
#pragma unroll
            for (int bp = 0; bp < 4; bp++) {
                uint32_t vb[4];
                const int jr = q * 16 + (lane & 7) + (lane & 8);
                const int nc = bp * 16 + ((lane >> 4) & 1) * 8;
                ldsm_x4t(vsb + (jr * 72 + nc) * 2, vb);
                mma16(o[2 * bp],     a, vb[0], vb[1]);
                mma16(o[2 * bp + 1], a, vb[2], vb[3]);
            }
            {
                uint32_t vb1[2];
                const int jr = q * 16 + (lane & 7) + (lane & 8);
                ldsm_x2t(vsb + (jr * 72 + 64) * 2, vb1);
                mma16(osum, a, vb1[0], vb1[1]);
            }
        }
        if (++st == 3) st = 0;
    }

    // ---- Normalize + store (row sums exact per-lane) ----
    const float inv_lo = 1.0f / osum[0];
    const float inv_hi = 1.0f / osum[2];
    __half* abase = att + ((size_t)b * SEQ) * INNER + h * DH;
#pragma unroll
    for (int nt = 0; nt < 8; nt++) {
        const int c = nt * 8 + 2 * t;
        *(uint32_t*)(abase + (size_t)i_lo * INNER + c) =
            packh2(o[nt][0] * inv_lo, o[nt][1] * inv_lo);
        *(uint32_t*)(abase + (size_t)i_hi * INNER + c) =
            packh2(o[nt][2] * inv_hi, o[nt][3] * inv_hi);
    }
}

// ---------------------------------------------------------------------------
extern "C" void kernel_launch(void* const* d_in, const int* in_sizes, int n_in,
                              void* d_out, int out_size)
{
    const float* x         = (const float*)d_in[0];
    const float* w_qkv     = (const float*)d_in[1];
    const float* w_out     = (const float*)d_in[2];
    const float* b_out     = (const float*)d_in[3];
    const float* log_scale = (const float*)d_in[4];
    float* out = (float*)d_out;

    __half *xh, *wqkvh, *wouth, *qkv, *att;
    cudaGetSymbolAddress((void**)&xh,    g_xh);
    cudaGetSymbolAddress((void**)&wqkvh, g_wqkvh);
    cudaGetSymbolAddress((void**)&wouth, g_wouth);
    cudaGetSymbolAddress((void**)&qkv,   g_qkv);
    cudaGetSymbolAddress((void**)&att,   g_att);

    constexpr int GEMM_SMEM = 3 * (128 * 40 + 32 * 72) * 2;        // 44544 B
    constexpr int ATTN_SMEM = (128 * 72 + 3 * 2 * 64 * 72) * 2;    // 73728 B
    cudaFuncSetAttribute(gemm_h<true, false>,
                         cudaFuncAttributeMaxDynamicSharedMemorySize, GEMM_SMEM);
    cudaFuncSetAttribute(gemm_h<false, true>,
                         cudaFuncAttributeMaxDynamicSharedMemorySize, GEMM_SMEM);
    cudaFuncSetAttribute(attn_kernel,
                         cudaFuncAttributeMaxDynamicSharedMemorySize, ATTN_SMEM);

    const int M = BATCH * SEQ;  // 16384

    // 0) fp32 -> fp16 converts (single merged launch)
    const int n0 = (M * DIMM) / 1024;
    const int n1 = (DIMM * QKVC) / 1024;
    const int n2 = (INNER * DIMM) / 1024;
    f2h3<<<n0 + n1 + n2, 256>>>(x, xh, n0, w_qkv, wqkvh, n1, w_out, wouth);

    // 1) QKV projection
    gemm_h<true, false><<<dim3(QKVC / 64, M / 128), 256, GEMM_SMEM>>>(
        xh, wqkvh, nullptr, qkv, M, QKVC, DIMM);

    // 2) Fused flash attention
    attn_kernel<<<dim3(SEQ / 128, HEADS, BATCH), 256, ATTN_SMEM>>>(
        qkv, log_scale, att);

    // 3) Output projection + bias -> fp32
    gemm_h<false, true><<<dim3(DIMM / 64, M / 128), 256, GEMM_SMEM>>>(
        att, wouth, b_out, out, M, DIMM, INNER);
}

// round 15
// speedup vs baseline: 1.0392x; 1.0392x over previous
#include <cuda_runtime.h>
#include <cuda_fp16.h>
#include <cstdint>

#define BATCH 8
#define SEQ   2048
#define DIMM  512
#define HEADS 8
#define DH    64
#define INNER 512
#define QKVC  1536
#define FULLM 0xffffffffu

// Scratch (fp16, static device globals — allocation-free)
__device__ __half g_xh[(size_t)BATCH * SEQ * DIMM];
__device__ __half g_wqkvh[(size_t)DIMM * QKVC];
__device__ __half g_wouth[(size_t)INNER * DIMM];
__device__ __half g_qkv[(size_t)BATCH * SEQ * QKVC];    // [b,n,3*inner]
__device__ __half g_att[(size_t)BATCH * SEQ * INNER];   // [b,n,h*64+d]

// ---------------------------------------------------------------------------
__device__ __forceinline__ uint32_t smem_u32(const void* p) {
    uint32_t a;
    asm("{ .reg .u64 t; cvta.to.shared.u64 t, %1; cvt.u32.u64 %0, t; }"
        : "=r"(a) : "l"(p));
    return a;
}
__device__ __forceinline__ void cp16(uint32_t s, const void* g) {
    asm volatile("cp.async.cg.shared.global [%0], [%1], 16;"
                 :: "r"(s), "l"(g) : "memory");
}
__device__ __forceinline__ void cp_commit() {
    asm volatile("cp.async.commit_group;" ::: "memory");
}
template<int N> __device__ __forceinline__ void cp_wait() {
    asm volatile("cp.async.wait_group %0;" :: "n"(N) : "memory");
}
__device__ __forceinline__ void ldsm_x4(uint32_t addr, uint32_t* r) {
    asm volatile("ldmatrix.sync.aligned.m8n8.x4.shared.b16 {%0,%1,%2,%3}, [%4];"
                 : "=r"(r[0]), "=r"(r[1]), "=r"(r[2]), "=r"(r[3]) : "r"(addr));
}
__device__ __forceinline__ void ldsm_x4t(uint32_t addr, uint32_t* r) {
    asm volatile("ldmatrix.sync.aligned.m8n8.x4.trans.shared.b16 {%0,%1,%2,%3}, [%4];"
                 : "=r"(r[0]), "=r"(r[1]), "=r"(r[2]), "=r"(r[3]) : "r"(addr));
}
__device__ __forceinline__ void ldsm_x2t(uint32_t addr, uint32_t* r) {
    asm volatile("ldmatrix.sync.aligned.m8n8.x2.trans.shared.b16 {%0,%1}, [%2];"
                 : "=r"(r[0]), "=r"(r[1]) : "r"(addr));
}
__device__ __forceinline__ void mma16(float* d, const uint32_t* a,
                                      uint32_t b0, uint32_t b1) {
    asm volatile(
        "mma.sync.aligned.m16n8k16.row.col.f32.f16.f16.f32 "
        "{%0,%1,%2,%3}, {%4,%5,%6,%7}, {%8,%9}, {%0,%1,%2,%3};"
        : "+f"(d[0]), "+f"(d[1]), "+f"(d[2]), "+f"(d[3])
        : "r"(a[0]), "r"(a[1]), "r"(a[2]), "r"(a[3]), "r"(b0), "r"(b1));
}
__device__ __forceinline__ uint32_t packh2(float x, float y) {
    const __half2 h = __floats2half2_rn(x, y);
    return *(const uint32_t*)&h;
}
__device__ __forceinline__ float ex2(float x) {
    float r;
    asm("ex2.approx.f32 %0, %1;" : "=f"(r) : "f"(x));
    return r;
}

// ---------------------------------------------------------------------------
// Merged fp32 -> fp16 convert over three segments (sizes in float4 chunks).
// ---------------------------------------------------------------------------
__global__ __launch_bounds__(256) void f2h3(
    const float* __restrict__ s0, __half* __restrict__ d0, int n0,
    const float* __restrict__ s1, __half* __restrict__ d1, int n1,
    const float* __restrict__ s2, __half* __restrict__ d2)
{
    int blk = blockIdx.x;
    const float* src;
    __half* dst;
    if (blk < n0)            { src = s0; dst = d0; }
    else if (blk < n0 + n1)  { src = s1; dst = d1; blk -= n0; }
    else                     { src = s2; dst = d2; blk -= n0 + n1; }
    const int i = (blk * 256 + threadIdx.x) * 4;
    const float4 v = *(const float4*)(src + i);
    uint2 h;
    h.x = packh2(v.x, v.y);
    h.y = packh2(v.z, v.w);
    *(uint2*)(dst + i) = h;
}

// ---------------------------------------------------------------------------
// fp16 GEMM: block 128x128, BK=32, warp tile 32x64, 3-stage cp.async with
// strict commit cadence. Inner loop BATCHES all 6 ldmatrix issues before the
// 16-MMA burst (volatile-asm order = issue order; batching hides LDS latency).
// ---------------------------------------------------------------------------
template<bool C_HALF, bool BIAS>
__global__ __launch_bounds__(256, 2) void gemm_h(
    const __half* __restrict__ A, const __half* __restrict__ Bg,
    const float* __restrict__ bias, void* __restrict__ Cv,
    int M, int N, int K)
{
    extern __shared__ __half smg[];
    constexpr uint32_t ASZ = 128 * 40 * 2;     // pitch 40 halves
    constexpr uint32_t BSZ = 32 * 136 * 2;     // pitch 136 halves
    constexpr uint32_t SSZ = ASZ + BSZ;
    const uint32_t smb = smem_u32(smg);

    const int tid = threadIdx.x;
    const int wid = tid >> 5, lane = tid & 31;
    const int g = lane >> 2, t = lane & 3;
    const int wm = wid & 3, wn = wid >> 2;
    const int row0 = blockIdx.y * 128;
    const int col0 = blockIdx.x * 128;

    float acc[2][8][4];
#pragma unroll
    for (int mt = 0; mt < 2; mt++)
#pragma unroll
        for (int nt = 0; nt < 8; nt++)
#pragma unroll
            for (int i = 0; i < 4; i++) acc[mt][nt][i] = 0.f;

    auto load_tile = [&](int kb, int st) {
        const uint32_t ab = smb + st * SSZ;
        const uint32_t bb = ab + ASZ;
#pragma unroll
        for (int it = 0; it < 2; it++) {
            const int idx = tid + 256 * it;
            const int r = idx >> 2, c = (idx & 3) << 3;
            cp16(ab + (r * 40 + c) * 2, A + (size_t)(row0 + r) * K + kb + c);
        }
#pragma unroll
        for (int it = 0; it < 2; it++) {
            const int idx = tid + 256 * it;
            const int r = idx >> 4, c = (idx & 15) << 3;
            cp16(bb + (r * 136 + c) * 2, Bg + (size_t)(kb + r) * N + col0 + c);
        }
        cp_commit();
    };

    const int nch = K >> 5;
    load_tile(0, 0);
    load_tile(32, 1);

    int st = 0;
    for (int ch = 0; ch < nch; ch++) {
        cp_wait<1>();
        __syncthreads();
        if (ch + 2 < nch) {
            int ns = st + 2; if (ns >= 3) ns -= 3;
            load_tile((ch + 2) << 5, ns);
        } else {
            cp_commit();   // keep commit cadence exact at tail
        }

        const uint32_t asb = smb + st * SSZ;
        const uint32_t bsb = asb + ASZ;
#pragma unroll
        for (int kk = 0; kk < 32; kk += 16) {
            // ---- Batch ALL fragment loads first (6 ldmatrix issues) ----
            uint32_t a[2][4], b[4][4];
#pragma unroll
            for (int mt = 0; mt < 2; mt++) {
                const int r = wm * 32 + mt * 16 + (lane & 15);
                ldsm_x4(asb + (r * 40 + kk + ((lane >> 4) & 1) * 8) * 2, a[mt]);
            }
            const int kr = kk + (lane & 7) + (lane & 8);
#pragma unroll
            for (int bp = 0; bp < 4; bp++) {
                const int nc = wn * 64 + bp * 16 + ((lane >> 4) & 1) * 8;
                ldsm_x4t(bsb + (kr * 136 + nc) * 2, b[bp]);
            }
            // ---- Then the 16-MMA burst ----
#pragma unroll
            for (int bp = 0; bp < 4; bp++) {
                mma16(acc[0][2 * bp],     a[0], b[bp][0], b[bp][1]);
                mma16(acc[0][2 * bp + 1], a[0], b[bp][2], b[bp][3]);
                mma16(acc[1][2 * bp],     a[1], b[bp][0], b[bp][1]);
                mma16(acc[1][2 * bp + 1], a[1], b[bp][2], b[bp][3]);
            }
        }
        if (++st == 3) st = 0;
    }

#pragma unroll
    for (int mt = 0; mt < 2; mt++) {
        const int r_lo = row0 + wm * 32 + mt * 16 + g;
#pragma unroll
        for (int nt = 0; nt < 8; nt++) {
            const int c = col0 + wn * 64 + nt * 8 + 2 * t;
            if (C_HALF) {
                __half* C = (__half*)Cv;
                *(uint32_t*)(C + (size_t)r_lo * N + c) =
                    packh2(acc[mt][nt][0], acc[mt][nt][1]);
                *(uint32_t*)(C + (size_t)(r_lo + 8) * N + c) =
                    packh2(acc[mt][nt][2], acc[mt][nt][3]);
            } else {
                float* C = (float*)Cv;
                float2 lo = make_float2(acc[mt][nt][0], acc[mt][nt][1]);
                float2 hi = make_float2(acc[mt][nt][2], acc[mt][nt][3]);
                if (BIAS) {
                    lo.x += bias[c]; lo.y += bias[c + 1];
                    hi.x += bias[c]; hi.y += bias[c + 1];
                }
                *(float2*)(C + (size_t)r_lo * N + c) = lo;
                *(float2*)(C + (size_t)(r_lo + 8) * N + c) = hi;
            }
        }
    }
}

// ---------------------------------------------------------------------------
// Fused flash attention: 3-stage cp.async K/V pipeline (strict commit
// cadence), scale*log2e folded into Q, fp32 ex2 (no max), row sums via
// ones-column MMA, diag-mask only on its 2 tiles. Fragment loads batched
// ahead of every MMA burst. Block = (b,h,128 rows), 8 warps.
// ---------------------------------------------------------------------------
__global__ __launch_bounds__(256, 2) void attn_kernel(
    const __half* __restrict__ qkv, const float* __restrict__ lsp,
    __half* __restrict__ att)
{
    extern __shared__ __half sm[];
    constexpr uint32_t QSZ = 128 * 72 * 2;
    constexpr uint32_t KSZ = 64 * 72 * 2;
    const uint32_t smb = smem_u32(sm);

    const int i0 = blockIdx.x * 128;
    const int h = blockIdx.y;
    const int b = blockIdx.z;
    const int tid = threadIdx.x;
    const int wid = tid >> 5, lane = tid & 31;
    const int g = lane >> 2, t = lane & 3;

    const __half* qbase = qkv + ((size_t)b * SEQ) * QKVC + h * DH;
    const __half* kbase = qbase + INNER;
    const __half* vbase = qbase + 2 * INNER;
    const float c2 = __expf(lsp[0]) * 1.4426950408889634f;
    const __half2 c2h = __float2half2_rn(c2);

    auto load_kv = [&](int j0, int st) {
        const uint32_t kb = smb + QSZ + st * 2 * KSZ;
#pragma unroll
        for (int it = 0; it < 2; it++) {
            const int idx = tid + 256 * it;
            const int j = idx >> 3, c = (idx & 7) << 3;
            cp16(kb + (j * 72 + c) * 2, kbase + (size_t)(j0 + j) * QKVC + c);
            cp16(kb + KSZ + (j * 72 + c) * 2, vbase + (size_t)(j0 + j) * QKVC + c);
        }
        cp_commit();
    };

    load_kv(0, 0);
    load_kv(64, 1);

    // Ones pad columns (V cols 64..71) for all 3 stages
    if (tid < 192) {
        const int strow = tid / 64, row = tid & 63;
        const uint32_t voff = QSZ + strow * 2 * KSZ + KSZ;
        const __half2 one2 = __floats2half2_rn(1.f, 1.f);
        uint2 ones;
        ones.x = *(const uint32_t*)&one2;
        ones.y = ones.x;
        *(uint2*)((char*)sm + voff + (row * 72 + 64) * 2) = ones;
        *(uint2*)((char*)sm + voff + (row * 72 + 68) * 2) = ones;
    }

    // Stage Q tile, folding c2 into the fp16 values
#pragma unroll
    for (int it = 0; it < 4; it++) {
        const int idx = tid + 256 * it;
        const int r = idx >> 3, c8 = (idx & 7) << 3;
        uint4 v = *(const uint4*)(qbase + (size_t)(i0 + r) * QKVC + c8);
        __half2* hv = (__half2*)&v;
        hv[0] = __hmul2(hv[0], c2h);
        hv[1] = __hmul2(hv[1], c2h);
        hv[2] = __hmul2(hv[2], c2h);
        hv[3] = __hmul2(hv[3], c2h);
        *(uint4*)(sm + r * 72 + c8) = v;
    }
    __syncthreads();

    uint32_t qf[4][4];
#pragma unroll
    for (int kq = 0; kq < 4; kq++) {
        const int r = wid * 16 + (lane & 15);
        ldsm_x4(smb + (r * 72 + kq * 16 + ((lane >> 4) & 1) * 8) * 2, qf[kq]);
    }

    float o[8][4], osum[4];
#pragma unroll
    for (int nt = 0; nt < 8; nt++)
#pragma unroll
        for (int i = 0; i < 4; i++) o[nt][i] = 0.f;
#pragma unroll
    for (int i = 0; i < 4; i++) osum[i] = 0.f;

    const int i_lo = i0 + wid * 16 + g;
    const int i_hi = i_lo + 8;

    int st = 0;
    for (int j0 = 0; j0 < SEQ; j0 += 64) {
        cp_wait<1>();
        __syncthreads();
        if (j0 + 128 < SEQ) {
            int ns = st + 2; if (ns >= 3) ns -= 3;
            load_kv(j0 + 128, ns);
        } else {
            cp_commit();   // keep commit cadence exact at tail
        }

        const uint32_t ksb = smb + QSZ + st * 2 * KSZ;
        const uint32_t vsb = ksb + KSZ;

        // ---- S = (Q*c2) K^T : batch 4 K-fragment loads, then 8 MMAs ----
        float s[8][4];
#pragma unroll
        for (int nt = 0; nt < 8; nt++)
#pragma unroll
            for (int i = 0; i < 4; i++) s[nt][i] = 0.f;
#pragma unroll
        for (int kq = 0; kq < 4; kq++) {
            uint32_t kb4[4][4];
            const int kc = kq * 16 + (lane & 8);
#pragma unroll
            for (int bp = 0; bp < 4; bp++) {
                const int jr = bp * 16 + ((lane >> 4) & 1) * 8 + (lane & 7);
                ldsm_x4(ksb + (jr * 72 + kc) * 2, kb4[bp]);
            }
#pragma unroll
            for (int bp = 0; bp < 4; bp++) {
                mma16(s[2 * bp],     qf[kq], kb4[bp][0], kb4[bp][1]);
                mma16(s[2 * bp + 1], qf[kq], kb4[bp][2], kb4[bp][3]);
            }
        }

        // ---- p = exp2(s); diag -> 0 only on the 2 tiles containing it ----
        if (j0 == i0 || j0 == i0 + 64) {
#pragma unroll
            for (int nt = 0; nt < 8; nt++) {
                const int jc = j0 + nt * 8 + 2 * t;
                s[nt][0] = ex2((i_lo == jc)     ? -1e4f : s[nt][0]);
                s[nt][1] = ex2((i_lo == jc + 1) ? -1e4f : s[nt][1]);
                s[nt][2] = ex2((i_hi == jc)     ? -1e4f : s[nt][2]);
                s[nt][3] = ex2((i_hi == jc + 1) ? -1e4f : s[nt][3]);
            }
        } else {
#pragma unroll
            for (int nt = 0; nt < 8; nt++) {
                s[nt][0] = ex2(s[nt][0]);
                s[nt][1] = ex2(s[nt][1]);
                s[nt][2] = ex2(s[nt][2]);
                s[nt][3] = ex2(s[nt][3]);
            }
        }

        // ---- O += P V : batch 5 V-fragment loads, then 9 MMAs per q ----
#pragma unroll
        for (int q = 0; q < 4; q++) {
            uint32_t a[4];
            a[0] = packh2(s[2 * q][0],     s[2 * q][1]);
            a[1] = packh2(s[2 * q][2],     s[2 * q][3]);
            a[2] = packh2(s[2 * q + 1][0], s[2 * q + 1][1]);
            a[3] = packh2(s[2 * q + 1][2], s[2 * q + 1][3]);

            uint32_t vb[4][4], vb1[2];
            const int jr = q * 16 + (lane & 7) + (lane & 8);
#pragma unroll
            for (int bp = 0; bp < 4; bp++) {
                const int nc = bp * 16 + ((lane >> 4) & 1) * 8;
                ldsm_x4t(vsb + (jr * 72 + nc) * 2, vb[bp]);
            }
            ldsm_x2t(vsb + (jr * 72 + 64) * 2, vb1);
#pragma unroll
            for (int bp = 0; bp < 4; bp++) {
                mma16(o[2 * bp],     a, vb[bp][0], vb[bp][1]);
                mma16(o[2 * bp + 1], a, vb[bp][2], vb[bp][3]);
            }
            mma16(osum, a, vb1[0], vb1[1]);
        }
        if (++st == 3) st = 0;
    }

    // ---- Normalize + store ----
    const float inv_lo = 1.0f / osum[0];
    const float inv_hi = 1.0f / osum[2];
    __half* abase = att + ((size_t)b * SEQ) * INNER + h * DH;
#pragma unroll
    for (int nt = 0; nt < 8; nt++) {
        const int c = nt * 8 + 2 * t;
        *(uint32_t*)(abase + (size_t)i_lo * INNER + c) =
            packh2(o[nt][0] * inv_lo, o[nt][1] * inv_lo);
        *(uint32_t*)(abase + (size_t)i_hi * INNER + c) =
            packh2(o[nt][2] * inv_hi, o[nt][3] * inv_hi);
    }
}

// ---------------------------------------------------------------------------
extern "C" void kernel_launch(void* const* d_in, const int* in_sizes, int n_in,
                              void* d_out, int out_size)
{
    const float* x         = (const float*)d_in[0];
    const float* w_qkv     = (const float*)d_in[1];
    const float* w_out     = (const float*)d_in[2];
    const float* b_out     = (const float*)d_in[3];
    const float* log_scale = (const float*)d_in[4];
    float* out = (float*)d_out;

    __half *xh, *wqkvh, *wouth, *qkv, *att;
    cudaGetSymbolAddress((void**)&xh,    g_xh);
    cudaGetSymbolAddress((void**)&wqkvh, g_wqkvh);
    cudaGetSymbolAddress((void**)&wouth, g_wouth);
    cudaGetSymbolAddress((void**)&qkv,   g_qkv);
    cudaGetSymbolAddress((void**)&att,   g_att);

    constexpr int GEMM_SMEM = 3 * (128 * 40 + 32 * 136) * 2;       // 56832 B
    constexpr int ATTN_SMEM = (128 * 72 + 3 * 2 * 64 * 72) * 2;    // 73728 B
    cudaFuncSetAttribute(gemm_h<true, false>,
                         cudaFuncAttributeMaxDynamicSharedMemorySize, GEMM_SMEM);
    cudaFuncSetAttribute(gemm_h<false, true>,
                         cudaFuncAttributeMaxDynamicSharedMemorySize, GEMM_SMEM);
    cudaFuncSetAttribute(attn_kernel,
                         cudaFuncAttributeMaxDynamicSharedMemorySize, ATTN_SMEM);

    const int M = BATCH * SEQ;  // 16384

    // 0) fp32 -> fp16 converts (single merged launch)
    const int n0 = (M * DIMM) / 1024;
    const int n1 = (DIMM * QKVC) / 1024;
    const int n2 = (INNER * DIMM) / 1024;
    f2h3<<<n0 + n1 + n2, 256>>>(x, xh, n0, w_qkv, wqkvh, n1, w_out, wouth);

    // 1) QKV projection
    gemm_h<true, false><<<dim3(QKVC / 128, M / 128), 256, GEMM_SMEM>>>(
        xh, wqkvh, nullptr, qkv, M, QKVC, DIMM);

    // 2) Fused flash attention
    attn_kernel<<<dim3(SEQ / 128, HEADS, BATCH), 256, ATTN_SMEM>>>(
        qkv, log_scale, att);

    // 3) Output projection + bias -> fp32
    gemm_h<false, true><<<dim3(DIMM / 128, M / 128), 256, GEMM_SMEM>>>(
        att, wouth, b_out, out, M, DIMM, INNER);
}